// round 3
// baseline (speedup 1.0000x reference)
#include <cuda_runtime.h>
#include <cstdint>
#include <cstddef>

#define NMAX 100000
#define EMAX 3200000
#define NBLK_SCAN ((NMAX + 1023) / 1024)

// ---------------- static device scratch (no allocation anywhere) -------------
__device__ __align__(128) float g_h1[(size_t)NMAX * 256];   // relu(x@W1+b1)
__device__ __align__(128) float g_h [(size_t)NMAX * 64];    // MLP output
__device__ __align__(128) float g_bufA[(size_t)NMAX * 64];
__device__ __align__(128) float g_bufB[(size_t)NMAX * 64];
__device__ __align__(128) float g_dis[NMAX];                // 1/sqrt(deg)
__device__ __align__(128) int   g_cnt[NMAX];                // in-degree (no self loop)
__device__ __align__(128) int   g_incl[NMAX];               // scan scratch
__device__ __align__(128) int   g_bsum[NBLK_SCAN + 1];
__device__ __align__(128) int   g_rowptr[NMAX + 1];
__device__ __align__(128) int   g_cursor[NMAX];
__device__ __align__(128) int   g_col[EMAX];                // CSR column (src)
__device__ __align__(128) float g_w[EMAX];                  // CSR edge weight
__device__ int g_is64;                                      // edge_index dtype flag

__device__ __forceinline__ float* bufsel(int i) {
    return i == 0 ? g_h : (i == 1 ? g_bufA : g_bufB);
}

// Read edge endpoint j (0..2E-1) honoring detected dtype, clamped to [0,N)
__device__ __forceinline__ int edge_at(const void* ei, size_t j, int N) {
    long long v;
    if (g_is64) v = ((const long long*)ei)[j];
    else        v = (long long)((const int*)ei)[j];
    if (v < 0) v = 0;
    if (v >= N) v = N - 1;
    return (int)v;
}

// ---------------- dtype detection --------------------------------------------
// If the buffer is int32, interpreting it as int64 packs two random ints into
// one value -> virtually certain to leave [0, N). Check 4096 samples.
__global__ void k_detect(const void* ei, int E, int N) {
    __shared__ int bad;
    if (threadIdx.x == 0) bad = 0;
    __syncthreads();
    const long long* p = (const long long*)ei;
    int lim = (E < 4096) ? E : 4096;   // E int64 slots always within buffer bytes
    for (int i = threadIdx.x; i < lim; i += blockDim.x) {
        long long v = p[i];
        if (v < 0 || v >= (long long)N) bad = 1;
    }
    __syncthreads();
    if (threadIdx.x == 0) g_is64 = bad ? 0 : 1;
}

// ---------------- SGEMM: C = op(A@B + bias) ---------------------------------
template<int BM, int BN, int BK, int TM, int TN, int SEL>
__global__ void sgemm_kernel(const float* __restrict__ A_in,
                             const float* __restrict__ B,
                             const float* __restrict__ bias,
                             int M, int N, int K) {
    constexpr int NT = (BM / TM) * (BN / TN);
    constexpr bool RELU = (SEL == 0);
    const float* A = (SEL == 0) ? A_in : (const float*)g_h1;
    float* C       = (SEL == 0) ? g_h1 : g_h;

    __shared__ float As[BK][BM];
    __shared__ float Bs[BK][BN];

    const int tid  = threadIdx.x;
    const int row0 = blockIdx.y * BM;
    const int col0 = blockIdx.x * BN;

    const int tcols = BN / TN;
    const int tr = tid / tcols;
    const int tc = tid % tcols;

    float acc[TM][TN];
    #pragma unroll
    for (int i = 0; i < TM; i++)
        #pragma unroll
        for (int j = 0; j < TN; j++) acc[i][j] = 0.0f;

    constexpr int A_LD = (BM * BK) / (NT * 4);
    constexpr int B_LD = (BK * BN) / (NT * 4);

    for (int kt = 0; kt < K; kt += BK) {
        #pragma unroll
        for (int i = 0; i < A_LD; i++) {
            int idx = tid + i * NT;
            int a_r = idx / (BK / 4);
            int a_c = (idx % (BK / 4)) * 4;
            float4 v = make_float4(0.f, 0.f, 0.f, 0.f);
            int gr = row0 + a_r;
            if (gr < M)
                v = *reinterpret_cast<const float4*>(A + (size_t)gr * K + kt + a_c);
            As[a_c + 0][a_r] = v.x;
            As[a_c + 1][a_r] = v.y;
            As[a_c + 2][a_r] = v.z;
            As[a_c + 3][a_r] = v.w;
        }
        #pragma unroll
        for (int i = 0; i < B_LD; i++) {
            int idx = tid + i * NT;
            int b_r = idx / (BN / 4);
            int b_c = (idx % (BN / 4)) * 4;
            float4 v = *reinterpret_cast<const float4*>(B + (size_t)(kt + b_r) * N + col0 + b_c);
            *reinterpret_cast<float4*>(&Bs[b_r][b_c]) = v;
        }
        __syncthreads();

        #pragma unroll
        for (int kk = 0; kk < BK; kk++) {
            float ar[TM], br[TN];
            #pragma unroll
            for (int i = 0; i < TM; i++) ar[i] = As[kk][tr * TM + i];
            #pragma unroll
            for (int j = 0; j < TN; j++) br[j] = Bs[kk][tc * TN + j];
            #pragma unroll
            for (int i = 0; i < TM; i++)
                #pragma unroll
                for (int j = 0; j < TN; j++)
                    acc[i][j] = fmaf(ar[i], br[j], acc[i][j]);
        }
        __syncthreads();
    }

    #pragma unroll
    for (int i = 0; i < TM; i++) {
        int gr = row0 + tr * TM + i;
        if (gr >= M) continue;
        #pragma unroll
        for (int j = 0; j < TN; j += 4) {
            int gc = col0 + tc * TN + j;
            float4 b4 = *reinterpret_cast<const float4*>(bias + gc);
            float4 v;
            v.x = acc[i][j + 0] + b4.x;
            v.y = acc[i][j + 1] + b4.y;
            v.z = acc[i][j + 2] + b4.z;
            v.w = acc[i][j + 3] + b4.w;
            if (RELU) {
                v.x = fmaxf(v.x, 0.f); v.y = fmaxf(v.y, 0.f);
                v.z = fmaxf(v.z, 0.f); v.w = fmaxf(v.w, 0.f);
            }
            *reinterpret_cast<float4*>(C + (size_t)gr * N + gc) = v;
        }
    }
}

// ---------------- CSR construction -------------------------------------------
__global__ void k_zero_cnt(int n) {
    int i = blockIdx.x * blockDim.x + threadIdx.x;
    if (i < n) g_cnt[i] = 0;
}

__global__ void k_count(const void* __restrict__ ei, int E, int N) {
    int e = blockIdx.x * blockDim.x + threadIdx.x;
    if (e < E) {
        int d = edge_at(ei, (size_t)E + e, N);
        atomicAdd(&g_cnt[d], 1);
    }
}

__global__ void k_dis(int n) {
    int i = blockIdx.x * blockDim.x + threadIdx.x;
    if (i < n) g_dis[i] = rsqrtf((float)(g_cnt[i] + 1));  // +1 self loop
}

__global__ void k_scan1(int N) {
    __shared__ int sh[1024];
    int i = blockIdx.x * 1024 + threadIdx.x;
    int v = (i < N) ? g_cnt[i] : 0;
    sh[threadIdx.x] = v;
    __syncthreads();
    #pragma unroll
    for (int off = 1; off < 1024; off <<= 1) {
        int t = 0;
        if ((int)threadIdx.x >= off) t = sh[threadIdx.x - off];
        __syncthreads();
        sh[threadIdx.x] += t;
        __syncthreads();
    }
    if (i < N) g_incl[i] = sh[threadIdx.x];
    if (threadIdx.x == 1023) g_bsum[blockIdx.x] = sh[1023];
}

__global__ void k_scan2(int nb) {
    if (threadIdx.x == 0 && blockIdx.x == 0) {
        int acc = 0;
        for (int b = 0; b < nb; b++) {
            int v = g_bsum[b];
            g_bsum[b] = acc;
            acc += v;
        }
    }
}

__global__ void k_scan3(int N) {
    int i = blockIdx.x * 1024 + threadIdx.x;
    if (i < N) {
        int inc = g_incl[i] + g_bsum[i / 1024];
        g_rowptr[i + 1] = inc;
        g_cursor[i] = inc - g_cnt[i];      // exclusive prefix
    }
    if (i == 0) g_rowptr[0] = 0;
}

__global__ void k_fillcsr(const void* __restrict__ ei, int E, int N) {
    int e = blockIdx.x * blockDim.x + threadIdx.x;
    if (e >= E) return;
    int s = edge_at(ei, (size_t)e, N);
    int d = edge_at(ei, (size_t)E + e, N);
    int p = atomicAdd(&g_cursor[d], 1);
    if (p >= 0 && p < EMAX) {
        g_col[p] = s;
        g_w[p] = g_dis[s] * g_dis[d];
    }
}

// ---------------- propagation ------------------------------------------------
__global__ void k_init(float* __restrict__ out, const float* __restrict__ temp,
                       int n16) {
    int i = blockIdx.x * blockDim.x + threadIdx.x;
    if (i >= n16) return;
    float t0 = temp[0];
    float4 v = reinterpret_cast<const float4*>(g_h)[i];
    reinterpret_cast<float4*>(out)[i] =
        make_float4(t0 * v.x, t0 * v.y, t0 * v.z, t0 * v.w);
}

// Pull-SpMM fused with gamma-accumulation:
//   nxt[row] = dis[row]^2*cur[row] + sum_n w[n]*cur[col[n]]
//   out[row] += temp[k]*nxt[row]
// 16 threads per row, one float4 per thread.
__global__ void k_prop(int curi, int nxti, float* __restrict__ out,
                       const float* __restrict__ temp, int k, int N) {
    int t = blockIdx.x * blockDim.x + threadIdx.x;
    int row = t >> 4;
    if (row >= N) return;
    int f = (t & 15) << 2;

    const float* cur = bufsel(curi);
    float* nxt = bufsel(nxti);

    float d = g_dis[row];
    float d2 = d * d;
    float4 a = *reinterpret_cast<const float4*>(cur + (size_t)row * 64 + f);
    float ax = d2 * a.x, ay = d2 * a.y, az = d2 * a.z, aw = d2 * a.w;

    int beg = g_rowptr[row];
    int end = g_rowptr[row + 1];
    #pragma unroll 4
    for (int n = beg; n < end; n++) {
        int s = __ldg(&g_col[n]);
        float w = __ldg(&g_w[n]);
        float4 v = *reinterpret_cast<const float4*>(cur + (size_t)s * 64 + f);
        ax = fmaf(w, v.x, ax);
        ay = fmaf(w, v.y, ay);
        az = fmaf(w, v.z, az);
        aw = fmaf(w, v.w, aw);
    }

    size_t oi = (size_t)row * 64 + f;
    *reinterpret_cast<float4*>(nxt + oi) = make_float4(ax, ay, az, aw);

    float tk = temp[k];
    float4 o = *reinterpret_cast<const float4*>(out + oi);
    o.x = fmaf(tk, ax, o.x);
    o.y = fmaf(tk, ay, o.y);
    o.z = fmaf(tk, az, o.z);
    o.w = fmaf(tk, aw, o.w);
    *reinterpret_cast<float4*>(out + oi) = o;
}

// ---------------- launch ------------------------------------------------------
extern "C" void kernel_launch(void* const* d_in, const int* in_sizes, int n_in,
                              void* d_out, int out_size) {
    const float* x    = (const float*)d_in[0];
    const void*  ei   = (const void*)d_in[1];
    const float* W1   = (const float*)d_in[2];
    const float* b1   = (const float*)d_in[3];
    const float* W2   = (const float*)d_in[4];
    const float* b2   = (const float*)d_in[5];
    const float* temp = (const float*)d_in[6];
    float* out = (float*)d_out;

    const int HID = in_sizes[3];                 // 256
    const int OUT = in_sizes[5];                 // 64
    const int INF = in_sizes[2] / HID;           // 512
    const int N   = in_sizes[0] / INF;           // 100000
    const int E   = in_sizes[1] / 2;             // 3200000

    // ---- dtype detection for edge_index ----
    k_detect<<<1, 256>>>(ei, E, N);

    // ---- MLP ----
    {
        dim3 g(HID / 128, (N + 127) / 128);
        sgemm_kernel<128, 128, 16, 8, 8, 0><<<g, 256>>>(x, W1, b1, N, HID, INF);
    }
    {
        dim3 g(OUT / 64, (N + 127) / 128);
        sgemm_kernel<128, 64, 16, 8, 4, 1><<<g, 256>>>(nullptr, W2, b2, N, OUT, HID);
    }

    // ---- CSR build + gcn_norm ----
    k_zero_cnt<<<(N + 255) / 256, 256>>>(N);
    k_count  <<<(E + 255) / 256, 256>>>(ei, E, N);
    k_dis    <<<(N + 255) / 256, 256>>>(N);
    const int nblk = (N + 1023) / 1024;
    k_scan1  <<<nblk, 1024>>>(N);
    k_scan2  <<<1, 32>>>(nblk);
    k_scan3  <<<nblk, 1024>>>(N);
    k_fillcsr<<<(E + 255) / 256, 256>>>(ei, E, N);

    // ---- GPR propagation ----
    const int n16 = N * 16;
    k_init<<<(n16 + 255) / 256, 256>>>(out, temp, n16);

    int cur = 0, nxt = 1;
    const int K = 10;
    for (int k = 1; k <= K; k++) {
        k_prop<<<(n16 + 255) / 256, 256>>>(cur, nxt, out, temp, k, N);
        int t = cur;
        cur = nxt;
        nxt = (t == 0) ? 2 : t;
    }
}